// round 1
// baseline (speedup 1.0000x reference)
#include <cuda_runtime.h>
#include <math.h>

// Problem constants
#define NJ   16384          // n_min = N[2]
#define JT   64             // j-tile per block
#define NB   (NJ / JT)      // 256 blocks
#define YD   7              // 7 p-groups of 3 rows each (21 rows)

// Output layout (flattened tuple): [2][21][21][16384] A, [1] logdet, [2][344064] zout
#define A_PART  (21 * 21 * 16384)       // 7225344
#define LD_OFF  (2 * A_PART)            // 14450688
#define Z_OFF   (LD_OFF + 1)
#define Z_PART  (21 * 16384)            // 344064

__device__ float g_partial[NB];

__global__ __launch_bounds__(JT * YD) void gp_main(
    const float* __restrict__ l00r, const float* __restrict__ l00i,
    const float* __restrict__ l01r, const float* __restrict__ l01i,
    const float* __restrict__ l02r, const float* __restrict__ l02i,
    const float* __restrict__ l11r, const float* __restrict__ l11i,
    const float* __restrict__ l12r, const float* __restrict__ l12i,
    const float* __restrict__ l22r, const float* __restrict__ l22i,
    const float* __restrict__ zre,  const float* __restrict__ zim,
    float* __restrict__ out)
{
    // per-j state in shared, [var][JT] layout (conflict-free: lane == j offset)
    __shared__ float sm[156 * JT];
    __shared__ float sRed[2];
    float* sT1r  = sm;              // [16][JT]  index t*4+k
    float* sT1i  = sm + 16 * JT;
    float* sIS1r = sm + 32 * JT;    // [4][JT]
    float* sIS1i = sm + 36 * JT;
    float* sAr   = sm + 40 * JT;    // [16][JT]  1/lam00
    float* sAi   = sm + 56 * JT;
    float* sT2r  = sm + 72 * JT;    // [20][JT]
    float* sT2i  = sm + 92 * JT;
    float* sIS2r = sm + 112 * JT;   // [JT]
    float* sIS2i = sm + 113 * JT;
    float* sZr   = sm + 114 * JT;   // [21][JT]
    float* sZi   = sm + 135 * JT;

    const int jj   = threadIdx.x;
    const int j    = blockIdx.x * JT + jj;
    const int flat = threadIdx.x + JT * threadIdx.y;

    // cooperative z preload (all 448 threads)
    for (int idx = flat; idx < 21 * JT; idx += JT * YD) {
        int q = idx / JT, c = idx - q * JT;
        int gi = q * NJ + blockIdx.x * JT + c;
        sZr[idx] = zre[gi];
        sZi[idx] = zim[gi];
    }

    // ---------------- Phase 1: per-j recursion state (y == 0 threads) --------
    if (threadIdx.y == 0) {
        float ldacc = 0.f;
        float M2r = 0.f, M2i = 0.f;
#pragma unroll
        for (int t = 0; t < 4; ++t) {
            const int m = t * NJ + j;              // n1 index
            float S1r = l11r[m], S1i = l11i[m];
            float T1re[4], T1im[4], Are[4], Aim[4];
#pragma unroll
            for (int k = 0; k < 4; ++k) {
                const int i0 = k * 65536 + m;      // n0 index
                float br = l00r[i0], bi = l00i[i0];
                float nrm = br * br + bi * bi;
                float rn = 1.0f / nrm;
                float ar = br * rn, ai = -bi * rn; // 1/lam00
                float cr = l01r[i0], ci = l01i[i0];
                float bn = cr * cr + ci * ci;      // |lam01|^2
                S1r -= bn * ar;  S1i -= bn * ai;   // M1 = sum |B|^2 * (1/lam00)
                T1re[k] = cr * ar - ci * ai;       // T1 = lam01/lam00
                T1im[k] = cr * ai + ci * ar;
                Are[k] = ar; Aim[k] = ai;
                ldacc += logf(nrm);
                sT1r[(t * 4 + k) * JT + jj] = T1re[k];
                sT1i[(t * 4 + k) * JT + jj] = T1im[k];
                sAr [(t * 4 + k) * JT + jj] = ar;
                sAi [(t * 4 + k) * JT + jj] = ai;
            }
            float ns = S1r * S1r + S1i * S1i;
            float rs = 1.0f / ns;
            float is1r = S1r * rs, is1i = -S1i * rs;   // 1/S1
            ldacc += logf(ns);
            sIS1r[t * JT + jj] = is1r;
            sIS1i[t * JT + jj] = is1i;

            // Bvec[a, m_t]:  a<4 -> lam02[(a*4+t)*NJ + j],  a=4 -> lam12[t*NJ + j]
            float Br[5], Bi[5];
#pragma unroll
            for (int a = 0; a < 4; ++a) {
                const int ib = (a * 4 + t) * NJ + j;
                Br[a] = l02r[ib]; Bi[a] = l02i[ib];
            }
            { const int ib = t * NJ + j; Br[4] = l12r[ib]; Bi[4] = l12i[ib]; }

            // G = sum_{a<4} B_a conj(T1_a) - B_4
            float Gr = -Br[4], Gi = -Bi[4];
#pragma unroll
            for (int a = 0; a < 4; ++a) {
                Gr += Br[a] * T1re[a] + Bi[a] * T1im[a];
                Gi += Bi[a] * T1re[a] - Br[a] * T1im[a];
            }
            // T2 rows i*4+t = u_i*G + D_i*B_i ; accumulate M2 += conj(B_i)*T2
#pragma unroll
            for (int i = 0; i < 4; ++i) {
                float ur = T1re[i] * is1r - T1im[i] * is1i;  // u_i = T1_i/S1
                float ui = T1re[i] * is1i + T1im[i] * is1r;
                float t2r = ur * Gr - ui * Gi + Are[i] * Br[i] - Aim[i] * Bi[i];
                float t2i = ur * Gi + ui * Gr + Are[i] * Bi[i] + Aim[i] * Br[i];
                sT2r[(i * 4 + t) * JT + jj] = t2r;
                sT2i[(i * 4 + t) * JT + jj] = t2i;
                M2r += Br[i] * t2r + Bi[i] * t2i;
                M2i += Br[i] * t2i - Bi[i] * t2r;
            }
            {   // i = 4: u_4 = -conj(1/S1), D_4 = 2i Im(1/S1)
                float ur = -is1r, ui = is1i;
                float d4 = 2.0f * is1i;
                float t2r = ur * Gr - ui * Gi - d4 * Bi[4];
                float t2i = ur * Gi + ui * Gr + d4 * Br[4];
                sT2r[(16 + t) * JT + jj] = t2r;
                sT2i[(16 + t) * JT + jj] = t2i;
                M2r += Br[4] * t2r + Bi[4] * t2i;
                M2i += Br[4] * t2i - Bi[4] * t2r;
            }
        }
        float S2r = l22r[j] - M2r, S2i = l22i[j] - M2i;
        float ns2 = S2r * S2r + S2i * S2i;
        float rs2 = 1.0f / ns2;
        sIS2r[jj] = S2r * rs2;
        sIS2i[jj] = -S2i * rs2;
        ldacc += logf(ns2);
        ldacc *= 0.5f;     // log|c| = 0.5 log(|c|^2)

        // deterministic warp reduce (2 warps in y==0)
#pragma unroll
        for (int off = 16; off; off >>= 1)
            ldacc += __shfl_down_sync(0xffffffffu, ldacc, off);
        if ((jj & 31) == 0) sRed[jj >> 5] = ldacc;
    }
    __syncthreads();
    if (flat == 0) g_partial[blockIdx.x] = sRed[0] + sRed[1];

    // ---------------- Phase 2: emit A (21x21), zout --------------------------
    // A[p][q] = w_p conj(x_q) + [p,q<20, p%4==q%4] (u conj(v) + D diag) + [p=q=20] 2i Im(1/S2)
    const float is2r = sIS2r[jj], is2i = sIS2i[jj];
#pragma unroll
    for (int pp = 0; pp < 3; ++pp) {
        const int p = threadIdx.y * 3 + pp;
        const int tt = p & 3;
        float wr, wi, upr = 0.f, upi = 0.f, is1i_p = 0.f;
        float dar = 0.f, dai = 0.f;          // diagonal correction for p==q
        if (p < 20) {
            float t2r = sT2r[p * JT + jj], t2i = sT2i[p * JT + jj];
            wr = t2r * is2r - t2i * is2i;    // w_p = T2_p / S2
            wi = t2r * is2i + t2i * is2r;
            float is1r = sIS1r[tt * JT + jj];
            is1i_p     = sIS1i[tt * JT + jj];
            const int i0 = p >> 2;
            if (i0 < 4) {
                float ar = sT1r[(tt * 4 + i0) * JT + jj];
                float ai = sT1i[(tt * 4 + i0) * JT + jj];
                upr = ar * is1r - ai * is1i_p;
                upi = ar * is1i_p + ai * is1r;
                dar = sAr[(tt * 4 + i0) * JT + jj];
                dai = sAi[(tt * 4 + i0) * JT + jj];
            } else {
                upr = -is1r; upi = is1i_p;
                dar = 0.f;   dai = 2.0f * is1i_p;   // D_4
            }
        } else {
            wr = -is2r; wi = is2i;           // w_20 = -conj(1/S2)
        }
        float zar = 0.f, zai = 0.f;
        const int rowbase = p * 21 * NJ + j;
        for (int q = 0; q < 21; ++q) {
            float xr, xi;
            if (q < 20) { xr = sT2r[q * JT + jj]; xi = sT2i[q * JT + jj]; }
            else        { xr = -1.f; xi = 0.f; }
            float cr = wr * xr + wi * xi;    // w * conj(x)
            float ci = wi * xr - wr * xi;
            if (p < 20 && q < 20 && ((p ^ q) & 3) == 0) {
                const int i1 = q >> 2;
                float vr, vi;
                if (i1 < 4) { vr = sT1r[(tt * 4 + i1) * JT + jj];
                              vi = sT1i[(tt * 4 + i1) * JT + jj]; }
                else        { vr = -1.f; vi = 0.f; }
                cr += upr * vr + upi * vi;   // u * conj(v)
                ci += upi * vr - upr * vi;
                if (p == q) { cr += dar; ci += dai; }
            }
            if (p == 20 && q == 20) ci += 2.0f * is2i;   // 1/S2 - conj(1/S2)
            out[rowbase + q * NJ]          = cr;
            out[A_PART + rowbase + q * NJ] = ci;
            float zr = sZr[q * JT + jj], zi = sZi[q * JT + jj];
            zar += cr * zr - ci * zi;
            zai += cr * zi + ci * zr;
        }
        out[Z_OFF + p * NJ + j]          = zar;
        out[Z_OFF + Z_PART + p * NJ + j] = zai;
    }
}

__global__ void gp_finalize(float* __restrict__ out) {
    __shared__ float s[NB];
    s[threadIdx.x] = g_partial[threadIdx.x];
    __syncthreads();
#pragma unroll
    for (int off = NB / 2; off; off >>= 1) {
        if (threadIdx.x < off) s[threadIdx.x] += s[threadIdx.x + off];
        __syncthreads();
    }
    if (threadIdx.x == 0) out[LD_OFF] = s[0];
}

extern "C" void kernel_launch(void* const* d_in, const int* in_sizes, int n_in,
                              void* d_out, int out_size) {
    const float* l00r = (const float*)d_in[0];
    const float* l00i = (const float*)d_in[1];
    const float* l01r = (const float*)d_in[2];
    const float* l01i = (const float*)d_in[3];
    const float* l02r = (const float*)d_in[4];
    const float* l02i = (const float*)d_in[5];
    const float* l11r = (const float*)d_in[6];
    const float* l11i = (const float*)d_in[7];
    const float* l12r = (const float*)d_in[8];
    const float* l12i = (const float*)d_in[9];
    const float* l22r = (const float*)d_in[10];
    const float* l22i = (const float*)d_in[11];
    const float* zre  = (const float*)d_in[12];
    const float* zim  = (const float*)d_in[13];
    float* out = (float*)d_out;

    dim3 block(JT, YD, 1);
    gp_main<<<NB, block>>>(l00r, l00i, l01r, l01i, l02r, l02i,
                           l11r, l11i, l12r, l12i, l22r, l22i,
                           zre, zim, out);
    gp_finalize<<<1, NB>>>(out);
}

// round 3
// speedup vs baseline: 1.8816x; 1.8816x over previous
#include <cuda_runtime.h>

#define NJ 16384
#define JT 64
#define NB (NJ / JT)        // 256 blocks
#define NT 448              // threads per block

#define A_PART (21 * 21 * 16384)
#define LD_OFF (2 * A_PART)
#define Z_OFF  (LD_OFF + 1)
#define Z_PART (21 * 16384)

__device__ float g_partial[NB];
__device__ unsigned int g_done;   // zero-init; reset by last block each launch

struct f4 { float v[4]; };
__device__ __forceinline__ f4 ld4(const float* p) {
    float4 t = *(const float4*)p;
    f4 r; r.v[0] = t.x; r.v[1] = t.y; r.v[2] = t.z; r.v[3] = t.w; return r;
}
__device__ __forceinline__ void st4(float* p, const float* a) {
    *(float4*)p = make_float4(a[0], a[1], a[2], a[3]);
}

__global__ __launch_bounds__(NT) void gp_main(
    const float* __restrict__ l00r, const float* __restrict__ l00i,
    const float* __restrict__ l01r, const float* __restrict__ l01i,
    const float* __restrict__ l02r, const float* __restrict__ l02i,
    const float* __restrict__ l11r, const float* __restrict__ l11i,
    const float* __restrict__ l12r, const float* __restrict__ l12i,
    const float* __restrict__ l22r, const float* __restrict__ l22i,
    const float* __restrict__ zre,  const float* __restrict__ zim,
    float* __restrict__ out)
{
    __shared__ __align__(16) float sm[182 * JT];
    __shared__ float sRed[10];
    __shared__ float sF[NB];
    __shared__ unsigned int sLast;

    float* sT1r  = sm;              // [16][JT]  row t*4+k
    float* sT1i  = sm + 16 * JT;
    float* sIS1r = sm + 32 * JT;    // [4][JT]
    float* sIS1i = sm + 36 * JT;
    float* sAr   = sm + 40 * JT;    // [16][JT]
    float* sAi   = sm + 56 * JT;
    float* sT2r  = sm + 72 * JT;    // [20][JT]
    float* sT2i  = sm + 92 * JT;
    float* sIS2r = sm + 112 * JT;   // [JT]
    float* sIS2i = sm + 113 * JT;
    float* sZr   = sm + 114 * JT;   // [21][JT]
    float* sZi   = sm + 135 * JT;
    float* sM2pr = sm + 156 * JT;   // [4][JT] per-t partials
    float* sM2pi = sm + 160 * JT;
    float* sDXpr = sm + 164 * JT;   // [4][JT]
    float* sDXpi = sm + 168 * JT;
    float* sDYr  = sm + 172 * JT;   // [4][JT]
    float* sDYi  = sm + 176 * JT;
    float* sDXr  = sm + 180 * JT;   // [JT]
    float* sDXi  = sm + 181 * JT;

    const int flat = threadIdx.x;
    const int jj   = flat & 63;
    const int t    = flat >> 6;          // 0..6
    const int j    = blockIdx.x * JT + jj;

    // ---- z preload (all threads) ----
    for (int idx = flat; idx < 21 * JT; idx += NT) {
        int q = idx >> 6, c = idx & 63;
        int gi = q * NJ + blockIdx.x * JT + c;
        sZr[idx] = zre[gi];
        sZi[idx] = zim[gi];
    }
    __syncthreads();

    // ---- Phase 1: per-(t, j) recursion, t-parallel across warps 0..7 ----
    if (t < 4) {
        float ldacc = 0.f, M2r = 0.f, M2i = 0.f, dxr = 0.f, dxi = 0.f;
        const int m = t * NJ + j;
        float S1r = l11r[m], S1i = l11i[m];
        float T1re[4], T1im[4], Are[4], Aim[4];
#pragma unroll
        for (int k = 0; k < 4; ++k) {
            const int i0 = k * 65536 + m;
            float br = l00r[i0], bi = l00i[i0];
            float nrm = br * br + bi * bi;
            float rn = 1.0f / nrm;
            float ar = br * rn, ai = -bi * rn;     // 1/lam00
            float cr = l01r[i0], ci = l01i[i0];
            float bn = cr * cr + ci * ci;
            S1r -= bn * ar;  S1i -= bn * ai;
            T1re[k] = cr * ar - ci * ai;
            T1im[k] = cr * ai + ci * ar;
            Are[k] = ar; Aim[k] = ai;
            ldacc += __logf(nrm);
            sT1r[(t * 4 + k) * JT + jj] = T1re[k];
            sT1i[(t * 4 + k) * JT + jj] = T1im[k];
            sAr [(t * 4 + k) * JT + jj] = ar;
            sAi [(t * 4 + k) * JT + jj] = ai;
        }
        float ns = S1r * S1r + S1i * S1i;
        float rs = 1.0f / ns;
        float is1r = S1r * rs, is1i = -S1i * rs;
        ldacc += __logf(ns);
        sIS1r[t * JT + jj] = is1r;
        sIS1i[t * JT + jj] = is1i;

        float Br[5], Bi[5];
#pragma unroll
        for (int a = 0; a < 4; ++a) {
            const int ib = (a * 4 + t) * NJ + j;
            Br[a] = l02r[ib]; Bi[a] = l02i[ib];
        }
        { const int ib = t * NJ + j; Br[4] = l12r[ib]; Bi[4] = l12i[ib]; }

        float Gr = -Br[4], Gi = -Bi[4];
#pragma unroll
        for (int a = 0; a < 4; ++a) {
            Gr += Br[a] * T1re[a] + Bi[a] * T1im[a];
            Gi += Bi[a] * T1re[a] - Br[a] * T1im[a];
        }
        // doty_t = sum_{i1<4} conj(T1_i1) z_{i1*4+t} - z_{16+t}
        {
            float dyr = 0.f, dyi = 0.f;
#pragma unroll
            for (int i1 = 0; i1 < 4; ++i1) {
                float zr = sZr[(i1 * 4 + t) * JT + jj], zi = sZi[(i1 * 4 + t) * JT + jj];
                dyr += T1re[i1] * zr + T1im[i1] * zi;
                dyi += T1re[i1] * zi - T1im[i1] * zr;
            }
            float zr = sZr[(16 + t) * JT + jj], zi = sZi[(16 + t) * JT + jj];
            dyr -= zr; dyi -= zi;
            sDYr[t * JT + jj] = dyr;
            sDYi[t * JT + jj] = dyi;
        }
        // T2 rows + M2 / dotx partials
#pragma unroll
        for (int i = 0; i < 5; ++i) {
            float t2r, t2i;
            if (i < 4) {
                float ur = T1re[i] * is1r - T1im[i] * is1i;
                float ui = T1re[i] * is1i + T1im[i] * is1r;
                t2r = ur * Gr - ui * Gi + Are[i] * Br[i] - Aim[i] * Bi[i];
                t2i = ur * Gi + ui * Gr + Are[i] * Bi[i] + Aim[i] * Br[i];
            } else {
                float ur = -is1r, ui = is1i;
                float d4 = 2.0f * is1i;
                t2r = ur * Gr - ui * Gi - d4 * Bi[4];
                t2i = ur * Gi + ui * Gr + d4 * Br[4];
            }
            const int row = (i < 4) ? (i * 4 + t) : (16 + t);
            sT2r[row * JT + jj] = t2r;
            sT2i[row * JT + jj] = t2i;
            M2r += Br[i] * t2r + Bi[i] * t2i;
            M2i += Br[i] * t2i - Bi[i] * t2r;
            float zr = sZr[row * JT + jj], zi = sZi[row * JT + jj];
            dxr += t2r * zr + t2i * zi;
            dxi += t2r * zi - t2i * zr;
        }
        sM2pr[t * JT + jj] = M2r;  sM2pi[t * JT + jj] = M2i;
        sDXpr[t * JT + jj] = dxr;  sDXpi[t * JT + jj] = dxi;

        ldacc *= 0.5f;
#pragma unroll
        for (int off = 16; off; off >>= 1)
            ldacc += __shfl_down_sync(0xffffffffu, ldacc, off);
        if ((flat & 31) == 0) sRed[flat >> 5] = ldacc;
    }
    __syncthreads();

    // ---- Phase 1.5: S2, 1/S2, dotx finalize (threads 0..63) ----
    if (flat < JT) {
        float M2r = sM2pr[flat] + sM2pr[JT + flat] + sM2pr[2 * JT + flat] + sM2pr[3 * JT + flat];
        float M2i = sM2pi[flat] + sM2pi[JT + flat] + sM2pi[2 * JT + flat] + sM2pi[3 * JT + flat];
        float S2r = l22r[j] - M2r, S2i = l22i[j] - M2i;
        float ns2 = S2r * S2r + S2i * S2i;
        float rs2 = 1.0f / ns2;
        sIS2r[flat] = S2r * rs2;
        sIS2i[flat] = -S2i * rs2;
        float dxr = sDXpr[flat] + sDXpr[JT + flat] + sDXpr[2 * JT + flat] + sDXpr[3 * JT + flat]
                  - sZr[20 * JT + flat];
        float dxi = sDXpi[flat] + sDXpi[JT + flat] + sDXpi[2 * JT + flat] + sDXpi[3 * JT + flat]
                  - sZi[20 * JT + flat];
        sDXr[flat] = dxr;
        sDXi[flat] = dxi;
        float ext = 0.5f * __logf(ns2);
#pragma unroll
        for (int off = 16; off; off >>= 1)
            ext += __shfl_down_sync(0xffffffffu, ext, off);
        if ((flat & 31) == 0) sRed[8 + (flat >> 5)] = ext;
    }
    __syncthreads();

    if (flat == 0) {
        float s = 0.f;
#pragma unroll
        for (int i = 0; i < 10; ++i) s += sRed[i];
        g_partial[blockIdx.x] = s;
        __threadfence();
        unsigned int old = atomicAdd(&g_done, 1u);
        sLast = (old == NB - 1) ? 1u : 0u;
    }

    // ---- Phase 2: emit A (21x21) + zout, 4 j per thread, vector stores ----
    if (flat < 336) {
        const int p   = flat >> 4;       // 0..20
        const int jq  = flat & 15;
        const int jj4 = jq * 4;
        const int j0  = blockIdx.x * JT + jj4;
        const int tt  = p & 3, i0 = p >> 2;

        f4 is2r = ld4(&sIS2r[jj4]), is2i = ld4(&sIS2i[jj4]);
        float wr[4], wi[4], ur[4], ui[4], dr[4], di[4];
        if (p < 20) {
            f4 t2r = ld4(&sT2r[p * JT + jj4]), t2i = ld4(&sT2i[p * JT + jj4]);
            f4 s1r = ld4(&sIS1r[tt * JT + jj4]), s1i = ld4(&sIS1i[tt * JT + jj4]);
#pragma unroll
            for (int e = 0; e < 4; ++e) {
                wr[e] = t2r.v[e] * is2r.v[e] - t2i.v[e] * is2i.v[e];
                wi[e] = t2r.v[e] * is2i.v[e] + t2i.v[e] * is2r.v[e];
            }
            if (i0 < 4) {
                f4 t1r = ld4(&sT1r[(tt * 4 + i0) * JT + jj4]);
                f4 t1i = ld4(&sT1i[(tt * 4 + i0) * JT + jj4]);
                f4 ar  = ld4(&sAr [(tt * 4 + i0) * JT + jj4]);
                f4 ai  = ld4(&sAi [(tt * 4 + i0) * JT + jj4]);
#pragma unroll
                for (int e = 0; e < 4; ++e) {
                    ur[e] = t1r.v[e] * s1r.v[e] - t1i.v[e] * s1i.v[e];
                    ui[e] = t1r.v[e] * s1i.v[e] + t1i.v[e] * s1r.v[e];
                    dr[e] = ar.v[e]; di[e] = ai.v[e];
                }
            } else {
#pragma unroll
                for (int e = 0; e < 4; ++e) {
                    ur[e] = -s1r.v[e]; ui[e] = s1i.v[e];
                    dr[e] = 0.f;       di[e] = 2.0f * s1i.v[e];
                }
            }
        } else {
#pragma unroll
            for (int e = 0; e < 4; ++e) {
                wr[e] = -is2r.v[e]; wi[e] = is2i.v[e];
                ur[e] = 0.f; ui[e] = 0.f;
                dr[e] = 0.f; di[e] = 2.0f * is2i.v[e];
            }
        }

        // zout_p = w*dotx + u*doty[tt] + d*z_p   (scalar stores: Z_OFF is odd)
        {
            f4 dxr = ld4(&sDXr[jj4]), dxi = ld4(&sDXi[jj4]);
            f4 dyr = ld4(&sDYr[tt * JT + jj4]), dyi = ld4(&sDYi[tt * JT + jj4]);
            f4 zpr = ld4(&sZr[p * JT + jj4]),  zpi = ld4(&sZi[p * JT + jj4]);
#pragma unroll
            for (int e = 0; e < 4; ++e) {
                float zar = wr[e] * dxr.v[e] - wi[e] * dxi.v[e]
                          + ur[e] * dyr.v[e] - ui[e] * dyi.v[e]
                          + dr[e] * zpr.v[e] - di[e] * zpi.v[e];
                float zai = wr[e] * dxi.v[e] + wi[e] * dxr.v[e]
                          + ur[e] * dyi.v[e] + ui[e] * dyr.v[e]
                          + dr[e] * zpi.v[e] + di[e] * zpr.v[e];
                out[Z_OFF + p * NJ + j0 + e]          = zar;
                out[Z_OFF + Z_PART + p * NJ + j0 + e] = zai;
            }
        }

        const int rowbase = p * 21 * NJ + j0;
#pragma unroll
        for (int q = 0; q < 21; ++q) {
            float cr[4], ci[4];
            if (q < 20) {
                f4 xr = ld4(&sT2r[q * JT + jj4]), xi = ld4(&sT2i[q * JT + jj4]);
#pragma unroll
                for (int e = 0; e < 4; ++e) {
                    cr[e] = wr[e] * xr.v[e] + wi[e] * xi.v[e];
                    ci[e] = wi[e] * xr.v[e] - wr[e] * xi.v[e];
                }
            } else {
#pragma unroll
                for (int e = 0; e < 4; ++e) { cr[e] = -wr[e]; ci[e] = -wi[e]; }
            }
            if (p < 20 && q < 20 && (((p ^ q) & 3) == 0)) {
                const int i1 = q >> 2;
                if (i1 < 4) {
                    f4 vr = ld4(&sT1r[(tt * 4 + i1) * JT + jj4]);
                    f4 vi = ld4(&sT1i[(tt * 4 + i1) * JT + jj4]);
#pragma unroll
                    for (int e = 0; e < 4; ++e) {
                        cr[e] += ur[e] * vr.v[e] + ui[e] * vi.v[e];
                        ci[e] += ui[e] * vr.v[e] - ur[e] * vi.v[e];
                    }
                } else {
#pragma unroll
                    for (int e = 0; e < 4; ++e) { cr[e] -= ur[e]; ci[e] -= ui[e]; }
                }
            }
            if (p == q) {
#pragma unroll
                for (int e = 0; e < 4; ++e) { cr[e] += dr[e]; ci[e] += di[e]; }
            }
            st4(&out[rowbase + q * NJ], cr);
            st4(&out[A_PART + rowbase + q * NJ], ci);
        }
    }

    // ---- fused logdet finalize (last block only; deterministic tree) ----
    __syncthreads();
    if (sLast) {
        if (flat < NB) sF[flat] = g_partial[flat];
        __syncthreads();
        for (int off = NB / 2; off; off >>= 1) {
            if (flat < off) sF[flat] += sF[flat + off];
            __syncthreads();
        }
        if (flat == 0) {
            out[LD_OFF] = sF[0];
            g_done = 0u;          // reset for next graph replay
        }
    }
}

extern "C" void kernel_launch(void* const* d_in, const int* in_sizes, int n_in,
                              void* d_out, int out_size) {
    const float* l00r = (const float*)d_in[0];
    const float* l00i = (const float*)d_in[1];
    const float* l01r = (const float*)d_in[2];
    const float* l01i = (const float*)d_in[3];
    const float* l02r = (const float*)d_in[4];
    const float* l02i = (const float*)d_in[5];
    const float* l11r = (const float*)d_in[6];
    const float* l11i = (const float*)d_in[7];
    const float* l12r = (const float*)d_in[8];
    const float* l12i = (const float*)d_in[9];
    const float* l22r = (const float*)d_in[10];
    const float* l22i = (const float*)d_in[11];
    const float* zre  = (const float*)d_in[12];
    const float* zim  = (const float*)d_in[13];
    float* out = (float*)d_out;

    gp_main<<<NB, NT>>>(l00r, l00i, l01r, l01i, l02r, l02i,
                        l11r, l11i, l12r, l12i, l22r, l22i,
                        zre, zim, out);
}